// round 12
// baseline (speedup 1.0000x reference)
#include <cuda_runtime.h>
#include <cuda_bf16.h>

// Problem constants: N=50000, E=800000, D=128, H=4, C=32
#define NMAX 50048
#define E2MAX 860000

__device__ float g_mu[NMAX];
__device__ float g_rstd[NMAX];
__device__ float g_hnorm[NMAX];
__device__ float g_xlr[NMAX * 256];    // [xl | xr] packed per node
__device__ int   g_count[NMAX];
__device__ int   g_rowoff[NMAX + 1];
__device__ int   g_cursor[NMAX];
__device__ int   g_csrc[E2MAX];
__device__ int   g_bsum[64];

// packed fp32x2 FMA (B300: 2 MACs/instr; exact IEEE fp32)
__device__ __forceinline__ void fma_f32x2(unsigned long long& d,
                                          unsigned long long a,
                                          unsigned long long b)
{
    asm("fma.rn.f32x2 %0, %1, %2, %0;" : "+l"(d) : "l"(a), "l"(b));
}

union U64F2 { unsigned long long u; float2 f; };

// ---------------------------------------------------------------------------
// Kernel 1: LN stats, warp-per-node (lane = 4 channels). No smem, no barriers.
// ---------------------------------------------------------------------------
__global__ __launch_bounds__(256) void ln_stats_kernel(
    const float* __restrict__ x, const float* __restrict__ gamma,
    const float* __restrict__ beta, int n)
{
    int gw = (blockIdx.x * blockDim.x + threadIdx.x) >> 5;   // node id
    int l = threadIdx.x & 31;
    if (gw >= n) return;

    float4 v = *(const float4*)&x[gw * 128 + l * 4];
    float s  = v.x + v.y + v.z + v.w;
    float s2 = v.x * v.x + v.y * v.y + v.z * v.z + v.w * v.w;
#pragma unroll
    for (int o = 16; o; o >>= 1) {
        s  += __shfl_xor_sync(0xffffffffu, s, o);
        s2 += __shfl_xor_sync(0xffffffffu, s2, o);
    }
    float mu  = s * (1.0f / 128.0f);
    float var = s2 * (1.0f / 128.0f) - mu * mu;
    float rstd = rsqrtf(var + 1e-5f);

    float4 gm = *(const float4*)&gamma[l * 4];
    float4 bt = *(const float4*)&beta[l * 4];
    float h0 = fmaxf((v.x - mu) * rstd * gm.x + bt.x, 0.f);
    float h1 = fmaxf((v.y - mu) * rstd * gm.y + bt.y, 0.f);
    float h2 = fmaxf((v.z - mu) * rstd * gm.z + bt.z, 0.f);
    float h3 = fmaxf((v.w - mu) * rstd * gm.w + bt.w, 0.f);
    float q = h0 * h0 + h1 * h1 + h2 * h2 + h3 * h3;
#pragma unroll
    for (int o = 16; o; o >>= 1) q += __shfl_xor_sync(0xffffffffu, q, o);

    if (l == 0) {
        g_mu[gw] = mu;
        g_rstd[gw] = rstd;
        g_hnorm[gw] = sqrtf(q);
        g_count[gw] = 0;
    }
}

// ---------------------------------------------------------------------------
// Kernel 2: fused LN+ReLU+SGEMM via packed f32x2 FMA.
// BM=64, BN=256, BK=32. A k-major pad 68; (a,a) packed operand built in regs.
// ---------------------------------------------------------------------------
__global__ __launch_bounds__(256) void gemm_kernel(
    const float* __restrict__ x, const float* __restrict__ gamma,
    const float* __restrict__ beta,
    const float* __restrict__ Wl, const float* __restrict__ bl,
    const float* __restrict__ Wr, const float* __restrict__ br, int n)
{
    __shared__ float As[32][68];
    __shared__ float Bs[32][256];

    int tid = threadIdx.x;
    int rowbase = blockIdx.x * 64;
    int rx = tid & 31;
    int ry = tid >> 5;

    unsigned long long acc[8][4];
#pragma unroll
    for (int r = 0; r < 8; r++)
#pragma unroll
        for (int c = 0; c < 4; c++) acc[r][c] = 0ull;

    for (int kt = 0; kt < 128; kt += 32) {
#pragma unroll
        for (int j = 0; j < 2; j++) {
            int idx = tid + j * 256;
            int row = idx >> 3;
            int q = idx & 7;
            int gr = rowbase + row;
            float4 hv = make_float4(0.f, 0.f, 0.f, 0.f);
            if (gr < n) {
                float4 v  = *(const float4*)&x[gr * 128 + kt + q * 4];
                float4 gm = *(const float4*)&gamma[kt + q * 4];
                float4 bt = *(const float4*)&beta[kt + q * 4];
                float mu = g_mu[gr], rs = g_rstd[gr];
                hv.x = fmaxf((v.x - mu) * rs * gm.x + bt.x, 0.f);
                hv.y = fmaxf((v.y - mu) * rs * gm.y + bt.y, 0.f);
                hv.z = fmaxf((v.z - mu) * rs * gm.z + bt.z, 0.f);
                hv.w = fmaxf((v.w - mu) * rs * gm.w + bt.w, 0.f);
            }
            As[q * 4 + 0][row] = hv.x;
            As[q * 4 + 1][row] = hv.y;
            As[q * 4 + 2][row] = hv.z;
            As[q * 4 + 3][row] = hv.w;
        }
#pragma unroll
        for (int j = 0; j < 8; j++) {
            int idx = tid + j * 256;
            int krow = idx >> 6;
            int col = (idx & 63) * 4;
            const float* src = (col < 128) ? &Wl[(kt + krow) * 128 + col]
                                           : &Wr[(kt + krow) * 128 + col - 128];
            *(float4*)&Bs[krow][col] = *(const float4*)src;
        }
        __syncthreads();

#pragma unroll
        for (int k = 0; k < 32; k++) {
            float a[8];
            *(float4*)&a[0] = *(float4*)&As[k][ry * 8];
            *(float4*)&a[4] = *(float4*)&As[k][ry * 8 + 4];
            ulonglong2 bq0 = *(const ulonglong2*)&Bs[k][rx * 8];
            ulonglong2 bq1 = *(const ulonglong2*)&Bs[k][rx * 8 + 4];
#pragma unroll
            for (int r = 0; r < 8; r++) {
                U64F2 ap;
                ap.f = make_float2(a[r], a[r]);
                fma_f32x2(acc[r][0], ap.u, bq0.x);
                fma_f32x2(acc[r][1], ap.u, bq0.y);
                fma_f32x2(acc[r][2], ap.u, bq1.x);
                fma_f32x2(acc[r][3], ap.u, bq1.y);
            }
        }
        __syncthreads();
    }

#pragma unroll
    for (int r = 0; r < 8; r++) {
        int gr = rowbase + ry * 8 + r;
        if (gr < n) {
#pragma unroll
            for (int c = 0; c < 8; c += 4) {
                int col = rx * 8 + c;
                const float* bb = (col < 128) ? &bl[col] : &br[col - 128];
                U64F2 p0, p1;
                p0.u = acc[r][c / 2];
                p1.u = acc[r][c / 2 + 1];
                float4 ov;
                ov.x = p0.f.x + bb[0];
                ov.y = p0.f.y + bb[1];
                ov.z = p1.f.x + bb[2];
                ov.w = p1.f.y + bb[3];
                *(float4*)&g_xlr[gr * 256 + col] = ov;
            }
        }
    }
}

// ---------------------------------------------------------------------------
// CSR build: hist -> scanA -> scanC -> scatter
// ---------------------------------------------------------------------------
__global__ void hist_kernel(const int* __restrict__ ei, int n, int e)
{
    int idx = blockIdx.x * blockDim.x + threadIdx.x;
    int e2 = e + n;
    if (idx >= e2) return;
    int d = (idx < e) ? __ldg(&ei[e + idx]) : (idx - e);
    if ((unsigned)d >= (unsigned)n) d = 0;
    atomicAdd(&g_count[d], 1);
}

__global__ __launch_bounds__(1024) void scanA_kernel(int n)
{
    __shared__ int ws[32];
    int i = blockIdx.x * 1024 + threadIdx.x;
    int t = threadIdx.x;
    int l = t & 31, w = t >> 5;
    int v = (i < n) ? g_count[i] : 0;

    int sc = v;
#pragma unroll
    for (int o = 1; o < 32; o <<= 1) {
        int u = __shfl_up_sync(0xffffffffu, sc, o);
        if (l >= o) sc += u;
    }
    if (l == 31) ws[w] = sc;
    __syncthreads();
    if (w == 0) {
        int q = (l < 32) ? ws[l] : 0;
#pragma unroll
        for (int o = 1; o < 32; o <<= 1) {
            int u = __shfl_up_sync(0xffffffffu, q, o);
            if (l >= o) q += u;
        }
        ws[l] = q;
    }
    __syncthreads();
    int excl = sc - v + (w ? ws[w - 1] : 0);
    if (i < n) g_rowoff[i] = excl;
    if (t == 1023) g_bsum[blockIdx.x] = excl + v;
}

__global__ __launch_bounds__(1024) void scanC_kernel(int n, int nblk)
{
    __shared__ int boff_sh;
    int t = threadIdx.x;
    if (t < 32) {
        int acc = 0;
        for (int b = t; b < blockIdx.x; b += 32) acc += g_bsum[b];
#pragma unroll
        for (int o = 16; o; o >>= 1) acc += __shfl_xor_sync(0xffffffffu, acc, o);
        if (t == 0) boff_sh = acc;
    }
    __syncthreads();
    int boff = boff_sh;
    int i = blockIdx.x * 1024 + t;
    if (i < n) {
        int v = g_rowoff[i] + boff;
        g_rowoff[i] = v;
        g_cursor[i] = v;
    }
    if (blockIdx.x == 0 && t < 32) {
        int tot = 0;
        for (int b = t; b < nblk; b += 32) tot += g_bsum[b];
#pragma unroll
        for (int o = 16; o; o >>= 1) tot += __shfl_xor_sync(0xffffffffu, tot, o);
        if (t == 0) g_rowoff[n] = tot;
    }
}

__global__ void scatter_kernel(const int* __restrict__ ei, int n, int e)
{
    int idx = blockIdx.x * blockDim.x + threadIdx.x;
    int e2 = e + n;
    if (idx >= e2) return;
    int s, d;
    if (idx < e) { s = __ldg(&ei[idx]); d = __ldg(&ei[e + idx]); }
    else         { s = idx - e; d = s; }
    if ((unsigned)s >= (unsigned)n) s = 0;
    if ((unsigned)d >= (unsigned)n) d = 0;
    int pos = atomicAdd(&g_cursor[d], 1);
    if (pos < E2MAX) g_csrc[pos] = s;
}

// ---------------------------------------------------------------------------
// Kernel 3: per-node GATv2, no-max softmax (exact: |score| << 88), SOFTWARE
// PIPELINED: iteration i+1's index load + feature gather issue before the
// compute of iteration i, overlapping the ~500cyc L2 chain with ~110cyc compute.
// Warp = head, lane = (edge-group g=l>>3, quad q=l&7), 4 edges/warp-iter.
// ---------------------------------------------------------------------------
__global__ __launch_bounds__(128) void gat_kernel(
    const float* __restrict__ x, const float* __restrict__ att,
    const float* __restrict__ bias, const float* __restrict__ scale_p,
    float* __restrict__ out, int n)
{
    int i = blockIdx.x;
    int t = threadIdx.x;
    int w = t >> 5;        // head
    int l = t & 31;
    int g = l >> 3;        // edge subgroup 0..3
    int q = l & 7;         // channel quad 0..7
    int cbase = w * 32 + q * 4;

    float4 xr4 = *(const float4*)&g_xlr[i * 256 + 128 + cbase];
    float4 at4 = *(const float4*)&att[cbase];
    int beg = g_rowoff[i];
    int end = g_rowoff[i + 1];   // end > beg always (self-loop)

    float s = 0.0f;
    float4 acc = make_float4(0.f, 0.f, 0.f, 0.f);

    // prologue: load edge 0 group
    int e0 = beg + g;
    bool valid = e0 < end;
    int j = g_csrc[valid ? e0 : beg];
    float4 v = *(const float4*)&g_xlr[j * 256 + cbase];

    for (int base = beg; base < end; base += 4) {
        // prefetch next iteration (safe fallback index beg)
        int en = base + 4 + g;
        bool valid_n = en < end;
        int j_n = g_csrc[valid_n ? en : beg];
        float4 v_n = *(const float4*)&g_xlr[j_n * 256 + cbase];

        // compute on current
        float z0 = v.x + xr4.x, z1 = v.y + xr4.y;
        float z2 = v.z + xr4.z, z3 = v.w + xr4.w;
        float p;
        p = at4.x * fmaxf(z0, 0.2f * z0);
        p = fmaf(at4.y, fmaxf(z1, 0.2f * z1), p);
        p = fmaf(at4.z, fmaxf(z2, 0.2f * z2), p);
        p = fmaf(at4.w, fmaxf(z3, 0.2f * z3), p);
        p += __shfl_xor_sync(0xffffffffu, p, 1);
        p += __shfl_xor_sync(0xffffffffu, p, 2);
        p += __shfl_xor_sync(0xffffffffu, p, 4);

        float wgt = valid ? __expf(p) : 0.0f;
        s += wgt;
        acc.x = fmaf(wgt, v.x, acc.x);
        acc.y = fmaf(wgt, v.y, acc.y);
        acc.z = fmaf(wgt, v.z, acc.z);
        acc.w = fmaf(wgt, v.w, acc.w);

        v = v_n;
        valid = valid_n;
    }

#pragma unroll
    for (int o = 8; o <= 16; o <<= 1) {
        s     += __shfl_xor_sync(0xffffffffu, s, o);
        acc.x += __shfl_xor_sync(0xffffffffu, acc.x, o);
        acc.y += __shfl_xor_sync(0xffffffffu, acc.y, o);
        acc.z += __shfl_xor_sync(0xffffffffu, acc.z, o);
        acc.w += __shfl_xor_sync(0xffffffffu, acc.w, o);
    }

    float inv_s = 1.0f / s;
    float4 b4 = *(const float4*)&bias[cbase];
    float o0 = acc.x * inv_s + b4.x;
    float o1 = acc.y * inv_s + b4.y;
    float o2 = acc.z * inv_s + b4.z;
    float o3 = acc.w * inv_s + b4.w;

    float qq = o0 * o0 + o1 * o1 + o2 * o2 + o3 * o3;
    qq += __shfl_xor_sync(0xffffffffu, qq, 1);
    qq += __shfl_xor_sync(0xffffffffu, qq, 2);
    qq += __shfl_xor_sync(0xffffffffu, qq, 4);
    __shared__ float sred[4];
    if (l == 0) sred[w] = qq;
    __syncthreads();
    float norm = sqrtf(sred[0] + sred[1] + sred[2] + sred[3]);

    float k = g_hnorm[i] * __ldg(&scale_p[0]) / fmaxf(norm, 1e-12f);
    if (g == 0) {
        const float4 xv = *(const float4*)&x[i * 128 + cbase];
        float4 ov;
        ov.x = xv.x + o0 * k;
        ov.y = xv.y + o1 * k;
        ov.z = xv.z + o2 * k;
        ov.w = xv.w + o3 * k;
        *(float4*)&out[i * 128 + cbase] = ov;
    }
}

// ---------------------------------------------------------------------------
extern "C" void kernel_launch(void* const* d_in, const int* in_sizes, int n_in,
                              void* d_out, int out_size)
{
    const float* x     = (const float*)d_in[0];
    const int*   ei    = (const int*)d_in[1];
    const float* gamma = (const float*)d_in[2];
    const float* beta  = (const float*)d_in[3];
    const float* Wl    = (const float*)d_in[4];
    const float* bl    = (const float*)d_in[5];
    const float* Wr    = (const float*)d_in[6];
    const float* br    = (const float*)d_in[7];
    const float* att   = (const float*)d_in[8];
    const float* bias  = (const float*)d_in[9];
    const float* scale = (const float*)d_in[10];
    float* out = (float*)d_out;

    int n = in_sizes[0] / 128;
    int e = in_sizes[1] / 2;
    int e2 = e + n;
    int nblk = (n + 1023) / 1024;

    ln_stats_kernel<<<(n * 32 + 255) / 256, 256>>>(x, gamma, beta, n);
    gemm_kernel<<<(n + 63) / 64, 256>>>(x, gamma, beta, Wl, bl, Wr, br, n);
    hist_kernel<<<(e2 + 255) / 256, 256>>>(ei, n, e);
    scanA_kernel<<<nblk, 1024>>>(n);
    scanC_kernel<<<nblk, 1024>>>(n, nblk);
    scatter_kernel<<<(e2 + 255) / 256, 256>>>(ei, n, e);
    gat_kernel<<<n, 128>>>(x, att, bias, scale, out, n);
}